// round 5
// baseline (speedup 1.0000x reference)
#include <cuda_runtime.h>

// Fused ModernNet inference — bank-conflict-free layouts + cooperative FC.
// pad(-1) -> conv5x5s2 (1->12) +posbias relu -> pad(-1) -> grouped conv5x5s2
// (3x: 8->4) +posbias relu -> fc 192x30 relu -> fc 30x10.
// 8 samples/block (warp-per-sample for convs, block-cooperative for FC).

#define SPB 8
#define NT  256

// ---- padded weight globals (filled by prep kernel each launch) ----
__device__ float gW1p[12 * 28];     // conv1 w: [ch][28] (25 + 3 zero pad)
__device__ float gW2p[12 * 228];    // conv2 w: [oc][ic*28 + k] (+4 tail pad)
__device__ float gW3t[30 * 192];    // fc1 w transposed: [n][192]

__global__ void prep_kernel(const float* __restrict__ H1w,
                            const float* __restrict__ H2w,
                            const float* __restrict__ H3w) {
    const int i = blockIdx.x * 256 + threadIdx.x;
    if (i < 336) {
        int ch = i / 28, r = i % 28;
        gW1p[i] = (r < 25) ? H1w[ch * 25 + r] : 0.f;
    }
    if (i < 2736) {
        int oc = i / 228, rem = i % 228;
        int ic = rem / 28, r = rem % 28;
        gW2p[i] = (ic < 8 && r < 25) ? H2w[oc * 200 + ic * 25 + r] : 0.f;
    }
    if (i < 5760) {
        int n = i / 192, k = i % 192;
        gW3t[i] = H3w[k * 30 + n];
    }
}

// c1 channel offset with bank-decollision swizzle (+8 floats for ch 4..7)
#define C1OFF(ch) ((ch) * 148 + ((((ch) >> 2) & 1) << 3))
#define C1_PER_SAMPLE 1776
#define W2_OC_STRIDE 228
#define C2_STRIDE 196        // 196 % 32 == 4 -> 8 samples on distinct banks
#define F1_STRIDE 36

// ---- shared memory float offsets (all multiples of 4) ----
#define OFF_W1   0       // 336
#define OFF_B1   336     // 768
#define OFF_W2   1104    // 2736
#define OFF_B2   3840    // 192
#define OFF_WOT  4032    // 10 * 36 = 360 (fc2 w transposed, zero-padded)
#define OFF_BO   4392    // 12
#define OFF_B3   4404    // 32
#define OFF_XIN  4436    // 8 * 400 (row-permuted 20x20)
#define OFF_C1   7636    // 8 * 1776
#define OFF_C2   21844   // 8 * 196
#define OFF_F1   23412   // 8 * 36 = 288
#define SMEM_FLOATS 23700   // 94800 bytes -> 2 blocks/SM

__global__ void __launch_bounds__(NT, 2) modernnet_kernel(
    const float* __restrict__ x,
    const float* __restrict__ H1b, const float* __restrict__ H2b,
    const float* __restrict__ H3b,
    const float* __restrict__ outw, const float* __restrict__ outb,
    float* __restrict__ out, int B)
{
    extern __shared__ float sm[];
    const int tid  = threadIdx.x;
    const int warp = tid >> 5;
    const int lane = tid & 31;
    const int blockSample = blockIdx.x * SPB;

    float* sW1  = sm + OFF_W1;
    float* sB1  = sm + OFF_B1;
    float* sW2  = sm + OFF_W2;
    float* sB2  = sm + OFF_B2;
    float* sWoT = sm + OFF_WOT;
    float* sBo  = sm + OFF_BO;
    float* sB3  = sm + OFF_B3;
    float* sXin = sm + OFF_XIN;
    float* sC1  = sm + OFF_C1;
    float* sC2  = sm + OFF_C2;
    float* sF1  = sm + OFF_F1;

    // ---------- Phase 0: weight copies + pad fills ----------
    {
        float4* d = (float4*)sW1;
        const float4* s = (const float4*)gW1p;
        for (int i = tid; i < 84; i += NT) d[i] = s[i];
    }
    {
        float4* d = (float4*)sB1;
        const float4* s = (const float4*)H1b;
        for (int i = tid; i < 192; i += NT) d[i] = s[i];
    }
    {
        float4* d = (float4*)sW2;
        const float4* s = (const float4*)gW2p;
        for (int i = tid; i < 684; i += NT) d[i] = s[i];
    }
    {
        float4* d = (float4*)sB2;
        const float4* s = (const float4*)H2b;
        for (int i = tid; i < 48; i += NT) d[i] = s[i];
    }
    for (int i = tid; i < 360; i += NT) {              // fc2 w transposed
        int m = i / 36, k = i % 36;
        sWoT[i] = (k < 30) ? outw[k * 10 + m] : 0.f;
    }
    if (tid < 12) sBo[tid] = (tid < 10) ? outb[tid] : 0.f;
    if (tid < 32) sB3[tid] = (tid < 30) ? H3b[tid] : 0.f;
    for (int i = tid; i < 288; i += NT) sF1[i] = 0.f;  // fc2 reads padded tail
    {
        const float4 m1 = make_float4(-1.f, -1.f, -1.f, -1.f);
        float4* f = (float4*)sXin;
        for (int i = tid; i < (SPB * 400) / 4; i += NT) f[i] = m1;
        float4* g = (float4*)sC1;
        for (int i = tid; i < (SPB * C1_PER_SAMPLE) / 4; i += NT) g[i] = m1;
    }
    // Fill -> scatter ordering across whole block (required!)
    __syncthreads();

    // ---------- Phase 1: inputs into row-PERMUTED padded 20x20 buffers ----
    // physical slot of logical row r: p(r) = (r&3)*5 + (r>>2)
    if (blockSample + SPB <= B) {
        const float4* gx = (const float4*)(x + (size_t)blockSample * 256);
        for (int i = tid; i < SPB * 64; i += NT) {
            float4 v = gx[i];
            int s = i >> 6, rem = i & 63;
            int ih = rem >> 2, iw = (rem & 3) * 4;
            int r = ih + 2;
            int slot = (r & 3) * 5 + (r >> 2);
            float* d = sXin + s * 400 + slot * 20 + iw + 2;
            ((float2*)d)[0] = make_float2(v.x, v.y);
            ((float2*)d)[1] = make_float2(v.z, v.w);
        }
    } else {
        const int nval = (B - blockSample) * 256;
        const float* gx = x + (size_t)blockSample * 256;
        for (int i = tid; i < nval; i += NT) {
            int s = i >> 8, p = i & 255;
            int ih = p >> 4, iw = p & 15;
            int r = ih + 2;
            int slot = (r & 3) * 5 + (r >> 2);
            sXin[s * 400 + slot * 20 + (iw + 2)] = gx[i];
        }
    }
    __syncthreads();

    // ---------- Phase 2: conv1 5x5 s2, 1->12 ch, posbias, relu ----------
    // lane: quad q (2x2 output pixels), channel-group chg of 6 channels
    {
        const int q   = lane & 15;
        const int chg = lane >> 4;
        const int oh0 = (q >> 2) << 1;
        const int ow0 = (q & 3) << 1;
        // logical row = 2*oh0 + i; slot = (i&3)*5 + (i>>2) + (oh0>>1)
        const float* pbase = sXin + warp * 400 + (oh0 >> 1) * 20 + 2 * ow0;

        float p[7][8];
        #pragma unroll
        for (int i = 0; i < 7; i++) {
            const int off = (((i & 3) * 5) + (i >> 2)) * 20;
            float4 v0 = *(const float4*)(pbase + off);
            float4 v1 = *(const float4*)(pbase + off + 4);
            p[i][0] = v0.x; p[i][1] = v0.y; p[i][2] = v0.z; p[i][3] = v0.w;
            p[i][4] = v1.x; p[i][5] = v1.y; p[i][6] = v1.z; p[i][7] = v1.w;
        }

        float* c1 = sC1 + warp * C1_PER_SAMPLE;
        #pragma unroll
        for (int cc = 0; cc < 6; cc++) {
            const int c = chg * 6 + cc;
            const float4* w4 = (const float4*)(sW1 + c * 28);
            float w[28];
            #pragma unroll
            for (int i = 0; i < 7; i++) {
                float4 v = w4[i];
                w[4 * i] = v.x; w[4 * i + 1] = v.y;
                w[4 * i + 2] = v.z; w[4 * i + 3] = v.w;
            }
            float a00 = 0.f, a01 = 0.f, a10 = 0.f, a11 = 0.f;
            #pragma unroll
            for (int ki = 0; ki < 5; ki++)
                #pragma unroll
                for (int kj = 0; kj < 5; kj++) {
                    const float wv = w[ki * 5 + kj];
                    a00 = fmaf(p[ki][kj],         wv, a00);
                    a01 = fmaf(p[ki][kj + 2],     wv, a01);
                    a10 = fmaf(p[ki + 2][kj],     wv, a10);
                    a11 = fmaf(p[ki + 2][kj + 2], wv, a11);
                }
            const float* b = sB1 + c * 64;
            float2 b0 = *(const float2*)(b + oh0 * 8 + ow0);
            float2 b1 = *(const float2*)(b + (oh0 + 1) * 8 + ow0);
            float* o = c1 + C1OFF(c);
            *(float2*)(o + (oh0 + 2) * 12 + ow0 + 2) =
                make_float2(fmaxf(a00 + b0.x, 0.f), fmaxf(a01 + b0.y, 0.f));
            *(float2*)(o + (oh0 + 3) * 12 + ow0 + 2) =
                make_float2(fmaxf(a10 + b1.x, 0.f), fmaxf(a11 + b1.y, 0.f));
        }
    }
    __syncwarp();

    // ---------- Phase 3: grouped conv2 5x5 s2, bias, relu ----------
    // lane<24: oc = lane>>1, half = lane&1 (output rows {0,1} / {2,3})
    if (lane < 24) {
        const int oc   = lane >> 1;
        const int half = lane & 1;
        const int g    = oc >> 2;
        const float* c1    = sC1 + warp * C1_PER_SAMPLE;
        const float* wbase = sW2 + oc * W2_OC_STRIDE;

        float acc[2][4];
        #pragma unroll
        for (int r = 0; r < 2; r++)
            #pragma unroll
            for (int c = 0; c < 4; c++) acc[r][c] = 0.f;

        #pragma unroll
        for (int ic = 0; ic < 8; ic++) {
            const int inch = ic + ((g == 1) ? 4 : ((g == 2 && ic >= 4) ? 4 : 0));
            const float* ib = c1 + C1OFF(inch) + half * 48;

            const float4* w4 = (const float4*)(wbase + ic * 28);
            float w[28];
            #pragma unroll
            for (int i = 0; i < 7; i++) {
                float4 v = w4[i];
                w[4 * i] = v.x; w[4 * i + 1] = v.y;
                w[4 * i + 2] = v.z; w[4 * i + 3] = v.w;
            }

            float rw[3][12];
            #define LOAD_ROW(s, r) do {                                        \
                float4 f0 = *(const float4*)(ib + (r) * 12);                   \
                float4 f1 = *(const float4*)(ib + (r) * 12 + 4);               \
                float4 f2 = *(const float4*)(ib + (r) * 12 + 8);               \
                rw[s][0] = f0.x; rw[s][1] = f0.y; rw[s][2]  = f0.z; rw[s][3]  = f0.w; \
                rw[s][4] = f1.x; rw[s][5] = f1.y; rw[s][6]  = f1.z; rw[s][7]  = f1.w; \
                rw[s][8] = f2.x; rw[s][9] = f2.y; rw[s][10] = f2.z; rw[s][11] = f2.w; \
            } while (0)

            LOAD_ROW(0, 0); LOAD_ROW(1, 1); LOAD_ROW(2, 2);

            #pragma unroll
            for (int ki = 0; ki < 5; ki++) {
                if (ki >= 1) LOAD_ROW((ki + 2) % 3, ki + 2);
                const int s0 = ki % 3, s1 = (ki + 2) % 3;
                #pragma unroll
                for (int kj = 0; kj < 5; kj++) {
                    const float wv = w[ki * 5 + kj];
                    #pragma unroll
                    for (int c = 0; c < 4; c++) {
                        acc[0][c] = fmaf(rw[s0][2 * c + kj], wv, acc[0][c]);
                        acc[1][c] = fmaf(rw[s1][2 * c + kj], wv, acc[1][c]);
                    }
                }
            }
            #undef LOAD_ROW
        }

        float* c2 = sC2 + warp * C2_STRIDE;
        const int rowb = oc * 16 + half * 8;
        float4 bA = *(const float4*)(sB2 + rowb);
        float4 bB = *(const float4*)(sB2 + rowb + 4);
        float4 oA, oB;
        oA.x = fmaxf(acc[0][0] + bA.x, 0.f); oA.y = fmaxf(acc[0][1] + bA.y, 0.f);
        oA.z = fmaxf(acc[0][2] + bA.z, 0.f); oA.w = fmaxf(acc[0][3] + bA.w, 0.f);
        oB.x = fmaxf(acc[1][0] + bB.x, 0.f); oB.y = fmaxf(acc[1][1] + bB.y, 0.f);
        oB.z = fmaxf(acc[1][2] + bB.z, 0.f); oB.w = fmaxf(acc[1][3] + bB.w, 0.f);
        *(float4*)(c2 + rowb)     = oA;
        *(float4*)(c2 + rowb + 4) = oB;
    }
    __syncthreads();   // fc1 reads all samples' sC2 -> block barrier

    // ---------- Phase 4: cooperative fc1 192->30, relu ----------
    // thread = (neuron n = tid>>3, sample s = tid&7); weights from gW3t[n][192]
    if (tid < 240) {
        const int n = tid >> 3, s = tid & 7;
        const float4* a4 = (const float4*)(sC2 + s * C2_STRIDE);
        const float4* w4 = (const float4*)(gW3t + n * 192);
        float acc0 = 0.f, acc1 = 0.f, acc2 = 0.f, acc3 = 0.f;
        #pragma unroll
        for (int i = 0; i < 48; i++) {
            float4 a = a4[i];
            float4 w = __ldg(w4 + i);
            acc0 = fmaf(a.x, w.x, acc0);
            acc1 = fmaf(a.y, w.y, acc1);
            acc2 = fmaf(a.z, w.z, acc2);
            acc3 = fmaf(a.w, w.w, acc3);
        }
        float acc = (acc0 + acc1) + (acc2 + acc3) + sB3[n];
        sF1[s * F1_STRIDE + n] = fmaxf(acc, 0.f);
    }
    __syncthreads();   // fc2 reads sF1 across warps

    // ---------- Phase 5: cooperative fc2 30->10 ----------
    // thread = (m = tid>>3, s = tid&7); sWoT rows zero-padded to 32
    if (tid < 80) {
        const int m = tid >> 3, s = tid & 7;
        const float4* f4 = (const float4*)(sF1 + s * F1_STRIDE);
        const float4* w4 = (const float4*)(sWoT + m * F1_STRIDE);
        float acc0 = 0.f, acc1 = 0.f, acc2 = 0.f, acc3 = 0.f;
        #pragma unroll
        for (int i = 0; i < 8; i++) {
            float4 a = f4[i];
            float4 w = w4[i];
            acc0 = fmaf(a.x, w.x, acc0);
            acc1 = fmaf(a.y, w.y, acc1);
            acc2 = fmaf(a.z, w.z, acc2);
            acc3 = fmaf(a.w, w.w, acc3);
        }
        const int smp = blockSample + s;
        if (smp < B)
            out[(size_t)smp * 10 + m] = (acc0 + acc1) + (acc2 + acc3) + sBo[m];
    }
}

extern "C" void kernel_launch(void* const* d_in, const int* in_sizes, int n_in,
                              void* d_out, int out_size) {
    const float* x    = (const float*)d_in[0];
    const float* H1w  = (const float*)d_in[1];
    const float* H1b  = (const float*)d_in[2];
    const float* H2w  = (const float*)d_in[3];
    const float* H2b  = (const float*)d_in[4];
    const float* H3w  = (const float*)d_in[5];
    const float* H3b  = (const float*)d_in[6];
    const float* outw = (const float*)d_in[7];
    const float* outb = (const float*)d_in[8];

    const int B = in_sizes[0] / 256;
    const int blocks = (B + SPB - 1) / SPB;
    const size_t smem = SMEM_FLOATS * sizeof(float);

    prep_kernel<<<24, 256>>>(H1w, H2w, H3w);

    cudaFuncSetAttribute(modernnet_kernel,
                         cudaFuncAttributeMaxDynamicSharedMemorySize, (int)smem);

    modernnet_kernel<<<blocks, NT, smem>>>(x, H1b, H2b, H3b, outw, outb,
                                           (float*)d_out, B);
}